// round 17
// baseline (speedup 1.0000x reference)
#include <cuda_runtime.h>
#include <math.h>

// Problem constants
#define B_  2
#define W_  4096
#define R_  8
#define D_  32
#define C_  64                 // chunk length
#define NC_ (W_ / C_)          // 64 chunks
#define GRID_ (B_ * NC_)       // 128 blocks (<= 148 SMs: all co-resident)

// Scratch + barrier state (device globals — no allocation allowed)
__device__ float g_L[B_ * NC_ * R_ * D_];   // per-chunk local decayed sums
// per-batch monotone arrival counters, padded to separate 128B lines
struct __align__(128) PadCtr { unsigned v; unsigned pad[31]; };
__device__ PadCtr g_barb[B_];               // never reset (monotone)

// ---------------------------------------------------------------------------
// Fused kernel (R15 skeleton; single change: Sin is a FLAT weighted sum with
// a precomputed weight table, killing the dependent L2 Horner chain).
//  Phase A: L_c[r,d] = gamma^63 * sum_j kg[r][j] h[j][d]   (kg = k*gamma^-j)
//  arrive:  fence + atomicAdd(g_barb[b])   [monotone across graph replays]
//  overlap: A matrix, full A·h accumulation, AND Sin weight table
//  wait:    t0 polls ld.acquire(g_barb[b]) >= (E/NC+1)*NC  (E read pre-arrive)
//  post:    Sin[r,d] = sum_cp wS[r][cp] * L[cp][r][d]  (independent loads);
//           += q*gamma*Sin; store.  No reset chain.
// ---------------------------------------------------------------------------
__global__ void __launch_bounds__(512, 1)
k_fused(const float* __restrict__ qin, const float* __restrict__ kin,
        const float* __restrict__ hin, const float* __restrict__ gamma,
        float* __restrict__ out)
{
    const int blk = blockIdx.x;
    const int b = blk / NC_, c = blk % NC_;
    const int w0 = c * C_;
    const int t = threadIdx.x;

    __shared__ float hs  [C_][D_];        // h chunk
    __shared__ float kgT [R_][C_];        // k * gamma^{-j}, transposed
    __shared__ float qg  [C_][R_];        // q * gamma^{i}
    __shared__ float A   [C_][C_ + 4];    // padded rows
    __shared__ float Sin [R_][D_];
    __shared__ float Pbuf[R_][D_];
    __shared__ float wS  [R_][NC_];       // Sin weights: gamma_r^{64*(c-1-cp)}
    __shared__ float gam_s[R_];

    // ---- entry epoch read (t0, BEFORE arriving; own batch counter) ----
    unsigned E = 0;
    if (t == 0) {
        asm volatile("ld.relaxed.gpu.global.u32 %0, [%1];"
                     : "=r"(E) : "l"(&g_barb[b].v) : "memory");
    }

    // ---- loads (float4) + decay pre-scaling ----
    {
        const float4* h4 = (const float4*)(hin + (size_t)(b * W_ + w0) * D_);
        ((float4*)hs)[t] = h4[t];         // 512 float4 = full 64x32 tile
    }
    if (t < 8) gam_s[t] = gamma[t];
    if (t < 128) {                        // k: 128 float4, transpose + gamma^-j
        const float4* k4 = (const float4*)(kin + (size_t)(b * W_ + w0) * R_);
        float4 v = k4[t];
        int j = t >> 1, r0 = (t & 1) * 4;
        float fj = -(float)j;
        kgT[r0 + 0][j] = v.x * exp2f(fj * __log2f(__ldg(&gamma[r0 + 0])));
        kgT[r0 + 1][j] = v.y * exp2f(fj * __log2f(__ldg(&gamma[r0 + 1])));
        kgT[r0 + 2][j] = v.z * exp2f(fj * __log2f(__ldg(&gamma[r0 + 2])));
        kgT[r0 + 3][j] = v.w * exp2f(fj * __log2f(__ldg(&gamma[r0 + 3])));
    } else if (t < 256) {                 // q: 128 float4, gamma^+i
        const float4* q4 = (const float4*)(qin + (size_t)(b * W_ + w0) * R_);
        int tt = t - 128;
        float4 v = q4[tt];
        int j = tt >> 1, r0 = (tt & 1) * 4;
        float fj = (float)j;
        qg[j][r0 + 0] = v.x * exp2f(fj * __log2f(__ldg(&gamma[r0 + 0])));
        qg[j][r0 + 1] = v.y * exp2f(fj * __log2f(__ldg(&gamma[r0 + 1])));
        qg[j][r0 + 2] = v.z * exp2f(fj * __log2f(__ldg(&gamma[r0 + 2])));
        qg[j][r0 + 3] = v.w * exp2f(fj * __log2f(__ldg(&gamma[r0 + 3])));
    }
    __syncthreads();

    // ---- Phase A: local decayed sums (512 threads: (half, r, d)) ----
    {
        const int d = t & 31, r = (t >> 5) & 7, half = t >> 8;
        const int j0 = half << 5;
        float a0 = 0.f, a1 = 0.f;
#pragma unroll
        for (int m = 0; m < 16; ++m) {
            a0 = fmaf(kgT[r][j0 + 2 * m],     hs[j0 + 2 * m][d],     a0);
            a1 = fmaf(kgT[r][j0 + 2 * m + 1], hs[j0 + 2 * m + 1][d], a1);
        }
        float part = a0 + a1;
        if (half == 0) Pbuf[r][d] = part;
        __syncthreads();
        if (half == 1) {
            float g63 = exp2f(63.f * __log2f(gam_s[r]));
            g_L[((b * NC_ + c) * R_ + r) * D_ + d] = g63 * (part + Pbuf[r][d]);
        }
    }
    __syncthreads();

    // ---- barrier arrive: fence-release then relaxed atomic (t0 only) ----
    if (t == 0) {
        __threadfence();
        atomicAdd(&g_barb[b].v, 1u);
    }

    // ---- Stage 1: A matrix (independent of g_L — overlaps other blocks) ----
    {
        const int i1 = t >> 3;            // 0..63
        const int jb = t & 7;             // 0..7
        float qr[8];
#pragma unroll
        for (int r = 0; r < 8; ++r) qr[r] = qg[i1][r];
#pragma unroll
        for (int jj = 0; jj < 8; ++jj) {
            const int j = jb + jj * 8;    // lanes hit consecutive j: no conflicts
            float a = 0.f;
#pragma unroll
            for (int r = 0; r < 8; ++r) a = fmaf(qr[r], kgT[r][j], a);
            A[i1][j] = (j <= i1) ? a : 0.f;
        }
    }

    // ---- Sin weight table (overlap window; one exp2f per thread) ----
    //      wS[r][cp] = gamma_r^{64*(c-1-cp)}  for cp < c
    {
        const int r = t >> 6, cp = t & 63;
        if (cp < c) {
            const float lg64 = 64.f * __log2f(gam_s[r]);
            wS[r][cp] = exp2f((float)(c - 1 - cp) * lg64);
        }
    }
    __syncthreads();                      // A + wS visible block-wide

    // ---- Stage 2a: intra-chunk A·h into registers (overlap window).
    //      Single j loop: each hs[j][d] loaded ONCE, feeds all 4 rows.
    const int w2 = t >> 5;                // 0..15
    const int d2 = t & 31;
    const int r0 = w2, r1 = 31 - w2;      // rows with len <= 32
    const int r2 = 32 + w2, r3 = 63 - w2; // rows with len <= 64
    float acc0 = 0.f, acc1 = 0.f, acc2 = 0.f, acc3 = 0.f;
    {
#pragma unroll
        for (int j4 = 0; j4 < 64; j4 += 4) {
            const float h0 = hs[j4 + 0][d2], h1 = hs[j4 + 1][d2];
            const float h2 = hs[j4 + 2][d2], h3 = hs[j4 + 3][d2];
            const float4 a2 = *(const float4*)&A[r2][j4];
            const float4 a3 = *(const float4*)&A[r3][j4];
            acc2 = fmaf(a2.x, h0, acc2); acc2 = fmaf(a2.y, h1, acc2);
            acc2 = fmaf(a2.z, h2, acc2); acc2 = fmaf(a2.w, h3, acc2);
            acc3 = fmaf(a3.x, h0, acc3); acc3 = fmaf(a3.y, h1, acc3);
            acc3 = fmaf(a3.z, h2, acc3); acc3 = fmaf(a3.w, h3, acc3);
            if (j4 < 32) {                // compile-time under full unroll
                const float4 a0 = *(const float4*)&A[r0][j4];
                const float4 a1 = *(const float4*)&A[r1][j4];
                acc0 = fmaf(a0.x, h0, acc0); acc0 = fmaf(a0.y, h1, acc0);
                acc0 = fmaf(a0.z, h2, acc0); acc0 = fmaf(a0.w, h3, acc0);
                acc1 = fmaf(a1.x, h0, acc1); acc1 = fmaf(a1.y, h1, acc1);
                acc1 = fmaf(a1.z, h2, acc1); acc1 = fmaf(a1.w, h3, acc1);
            }
        }
    }

    // ---- barrier wait: ACQUIRE-LOAD poll of own batch counter;
    //      launch-invariant target = (floor(E/NC)+1)*NC (monotone) ----
    if (t == 0 && c > 0) {
        const unsigned target = (E / (unsigned)NC_ + 1u) * (unsigned)NC_;
        unsigned v;
        do {
            asm volatile("ld.acquire.gpu.global.u32 %0, [%1];"
                         : "=r"(v) : "l"(&g_barb[b].v) : "memory");
        } while ((int)(v - target) < 0);
    }
    __syncthreads();

    // ---- Sin: FLAT weighted sum, parity-split over 512 threads.
    //      All loads independent -> one pipelined L2 round, no Horner chain.
    {
        const int p  = t >> 8;            // 0 or 1
        const int rd = t & 255;
        const int r = rd >> 5, dd = rd & 31;
        const float* Lp = g_L + (size_t)b * NC_ * R_ * D_ + r * D_ + dd;
        float sA = 0.f, sB = 0.f;
#pragma unroll 8
        for (int cp = p; cp < c; cp += 2) {
            const float lv = __ldcg(Lp + (size_t)cp * (R_ * D_));
            if ((cp >> 1) & 1) sB = fmaf(wS[r][cp], lv, sB);
            else               sA = fmaf(wS[r][cp], lv, sA);
        }
        const float s = sA + sB;
        if (p == 0) Pbuf[r][dd] = s;
        __syncthreads();
        if (p == 1) Sin[r][dd] = s + Pbuf[r][dd];
    }
    __syncthreads();

    // ---- Stage 2b: add inter-chunk term, store ----
    {
#pragma unroll
        for (int r = 0; r < 8; ++r) {
            const float gs = gam_s[r];
            const float sv = Sin[r][d2];
            acc0 = fmaf(qg[r0][r] * gs, sv, acc0);
            acc1 = fmaf(qg[r1][r] * gs, sv, acc1);
            acc2 = fmaf(qg[r2][r] * gs, sv, acc2);
            acc3 = fmaf(qg[r3][r] * gs, sv, acc3);
        }
        float* ob = out + (size_t)(b * W_ + w0) * D_ + d2;
        ob[(size_t)r0 * D_] = acc0;
        ob[(size_t)r1 * D_] = acc1;
        ob[(size_t)r2 * D_] = acc2;
        ob[(size_t)r3 * D_] = acc3;
    }
    // no reset: per-batch counters are monotone across graph replays
}

// ---------------------------------------------------------------------------
// Launch. Inputs (metadata order):
//   0: q_alpha [B,W,R]  1: k [B,W,R]  2: h_norm [B,W,D]
//   3: gamma_vec [R]    4: causal_mask (unused)  5: decay_diff (unused)
// out: float32 [B,W,D]
// ---------------------------------------------------------------------------
extern "C" void kernel_launch(void* const* d_in, const int* in_sizes, int n_in,
                              void* d_out, int out_size)
{
    const float* q     = (const float*)d_in[0];
    const float* k     = (const float*)d_in[1];
    const float* h     = (const float*)d_in[2];
    const float* gamma = (const float*)d_in[3];
    float* out         = (float*)d_out;

    k_fused<<<GRID_, 512>>>(q, k, h, gamma, out);
}